// round 1
// baseline (speedup 1.0000x reference)
#include <cuda_runtime.h>
#include <cstddef>

#define BB 4
#define CC 64
#define HH 160
#define WW 160
#define HWSZ (HH*WW)

// ---------------- scratch (device globals; no allocation allowed) ----------
__device__ float g_A32[BB*32*HWSZ];      // relu(conv3x3(x, ba_w1))
__device__ float g_gmap[BB*HWSZ];        // g = 1 + sigmoid(att + edge)
__device__ float g_smap[BB*HWSZ];        // s = g * sum_c x
__device__ float g_fusion[BB*64*HWSZ];
__device__ float g_t[BB*64*HWSZ];
__device__ float g_Weff[64*64];
__device__ float g_beff[64];

// ---------------- K0: effective dyn1d weights (sum over K) -----------------
__global__ void build_weff(const float* __restrict__ rk5w, const float* __restrict__ rk5b,
                           const float* __restrict__ rk7w, const float* __restrict__ rk7b,
                           const float* __restrict__ lk5w, const float* __restrict__ lk5b,
                           const float* __restrict__ lk7w, const float* __restrict__ lk7b)
{
    int id = blockIdx.x*blockDim.x + threadIdx.x;
    if (id >= 64*64) return;
    int m = id >> 6, c = id & 63;
    const float* w; const float* bs; int K, o;
    if      (m < 16) { w = rk5w; bs = rk5b; K = 5; o = m;    }
    else if (m < 32) { w = rk7w; bs = rk7b; K = 7; o = m-16; }
    else if (m < 48) { w = lk5w; bs = lk5b; K = 5; o = m-32; }
    else             { w = lk7w; bs = lk7b; K = 7; o = m-48; }
    float acc = 0.f;
    for (int k = 0; k < K; k++) acc += w[(o*K + k)*64 + c];
    g_Weff[m*64 + c] = acc;
    if (c == 0) {
        float bacc = 0.f;
        for (int k = 0; k < K; k++) bacc += bs[o*K + k];
        g_beff[m] = bacc;
    }
}

// ---------------- generic tiled 3x3 conv (pad=1) ---------------------------
// EPI: 0 = bias+relu, 1 = bias+bn+relu
template<int CIN, int COUT, int EPI>
__global__ __launch_bounds__(256)
void conv3x3_k(const float* __restrict__ in, const float* __restrict__ wt,
               const float* __restrict__ bias,
               const float* __restrict__ bng, const float* __restrict__ bnb,
               const float* __restrict__ bnm, const float* __restrict__ bnv,
               float* __restrict__ out)
{
    constexpr int NOC = COUT/2;
    constexpr int CI_CHUNK = 8;
    __shared__ float s_in[CI_CHUNK][18][18];
    __shared__ float s_w[CI_CHUNK][COUT][9];

    const int h0 = blockIdx.y*16, w0 = blockIdx.x*16;
    const int b  = blockIdx.z;
    const int tid = threadIdx.x;
    const int ocg = tid >> 7;           // 0 or 1
    const int pt  = tid & 127;
    const int px  = pt & 15;
    const int py0 = (pt >> 4) * 2;      // 0,2,...,14

    float acc0[NOC], acc1[NOC];
    #pragma unroll
    for (int i = 0; i < NOC; i++) { acc0[i] = 0.f; acc1[i] = 0.f; }

    for (int c0 = 0; c0 < CIN; c0 += CI_CHUNK) {
        // stage input tile (with halo, zero padded)
        for (int i = tid; i < CI_CHUNK*18*18; i += 256) {
            int ci = i / 324, rem = i % 324;
            int r = rem / 18, cc = rem % 18;
            int gh = h0 - 1 + r, gw = w0 - 1 + cc;
            float v = 0.f;
            if (gh >= 0 && gh < HH && gw >= 0 && gw < WW)
                v = in[((size_t)(b*CIN + c0 + ci))*HWSZ + gh*WW + gw];
            s_in[ci][r][cc] = v;
        }
        // stage weights
        for (int i = tid; i < CI_CHUNK*COUT*9; i += 256) {
            int ci = i / (COUT*9), rem = i % (COUT*9);
            int oc = rem / 9, k = rem % 9;
            s_w[ci][oc][k] = wt[((size_t)oc*CIN + c0 + ci)*9 + k];
        }
        __syncthreads();

        #pragma unroll 1
        for (int ci = 0; ci < CI_CHUNK; ci++) {
            float v[4][3];
            #pragma unroll
            for (int dr = 0; dr < 4; dr++)
                #pragma unroll
                for (int dc = 0; dc < 3; dc++)
                    v[dr][dc] = s_in[ci][py0 + dr][px + dc];
            #pragma unroll
            for (int oc = 0; oc < NOC; oc++) {
                const float* w9 = s_w[ci][ocg*NOC + oc];
                float a0 = 0.f, a1 = 0.f;
                #pragma unroll
                for (int dr = 0; dr < 3; dr++)
                    #pragma unroll
                    for (int dc = 0; dc < 3; dc++) {
                        float wv = w9[dr*3 + dc];
                        a0 += wv * v[dr][dc];
                        a1 += wv * v[dr+1][dc];
                    }
                acc0[oc] += a0; acc1[oc] += a1;
            }
        }
        __syncthreads();
    }

    #pragma unroll
    for (int oc = 0; oc < NOC; oc++) {
        int goc = ocg*NOC + oc;
        float v0 = acc0[oc] + bias[goc];
        float v1 = acc1[oc] + bias[goc];
        if (EPI == 1) {
            float sc = bng[goc] * rsqrtf(bnv[goc] + 1e-5f);
            float sh = bnb[goc] - bnm[goc]*sc;
            v0 = v0*sc + sh; v1 = v1*sc + sh;
        }
        v0 = fmaxf(v0, 0.f); v1 = fmaxf(v1, 0.f);
        size_t base = ((size_t)(b*COUT + goc))*HWSZ;
        out[base + (size_t)(h0 + py0    )*WW + (w0 + px)] = v0;
        out[base + (size_t)(h0 + py0 + 1)*WW + (w0 + px)] = v1;
    }
}

// ---------------- K2: edge (grouped sobel) + attention + g,s ---------------
// Grouped-conv semantics: output channel o uses filter o and input channel o/2.
// edge_mean = (1/32) * ( sum_{c<32} |sobel_x * x_c|  +  sum_{c>=32} |sobel_y * x_c| )
__global__ __launch_bounds__(256)
void edge_attn_k(const float* __restrict__ x,
                 const float* __restrict__ baw2, const float* __restrict__ bab2)
{
    __shared__ float s_in[8][18][18];
    const int h0 = blockIdx.y*16, w0 = blockIdx.x*16;
    const int b  = blockIdx.z;
    const int tid = threadIdx.x;
    const int px = tid & 15, py = tid >> 4;   // 16x16 pixels

    float edge = 0.f, sumx = 0.f;
    for (int c0 = 0; c0 < 64; c0 += 8) {
        for (int i = tid; i < 8*324; i += 256) {
            int ci = i / 324, rem = i % 324;
            int r = rem / 18, cc = rem % 18;
            int gh = h0 - 1 + r, gw = w0 - 1 + cc;
            float v = 0.f;
            if (gh >= 0 && gh < HH && gw >= 0 && gw < WW)
                v = x[((size_t)(b*64 + c0 + ci))*HWSZ + gh*WW + gw];
            s_in[ci][r][cc] = v;
        }
        __syncthreads();
        #pragma unroll 1
        for (int ci = 0; ci < 8; ci++) {
            float v00=s_in[ci][py  ][px], v01=s_in[ci][py  ][px+1], v02=s_in[ci][py  ][px+2];
            float v10=s_in[ci][py+1][px], v11=s_in[ci][py+1][px+1], v12=s_in[ci][py+1][px+2];
            float v20=s_in[ci][py+2][px], v21=s_in[ci][py+2][px+1], v22=s_in[ci][py+2][px+2];
            sumx += v11;
            if (c0 + ci < 32) {
                float gx = (v02 - v00) + 2.f*(v12 - v10) + (v22 - v20);
                edge += fabsf(gx);
            } else {
                float gy = (v20 - v00) + 2.f*(v21 - v01) + (v22 - v02);
                edge += fabsf(gy);
            }
        }
        __syncthreads();
    }
    edge *= (1.f/32.f);

    const int pix = (h0 + py)*WW + (w0 + px);
    float att = bab2[0];
    #pragma unroll 1
    for (int j = 0; j < 32; j++)
        att += baw2[j] * g_A32[((size_t)(b*32 + j))*HWSZ + pix];

    float z = att + edge;
    float a = 1.f / (1.f + expf(-z));
    float g = 1.f + a;
    g_gmap[(size_t)b*HWSZ + pix] = g;
    g_smap[(size_t)b*HWSZ + pix] = g * sumx;
}

// ---------------- K3: fusion = s * ( g * (Weff @ x) + beff ) ---------------
__global__ __launch_bounds__(256)
void fusion_k(const float* __restrict__ x)
{
    __shared__ float s_w[4096];
    __shared__ float s_be[64];
    const int tid = threadIdx.x;
    for (int i = tid; i < 4096; i += 256) s_w[i] = g_Weff[i];
    if (tid < 64) s_be[tid] = g_beff[tid];
    __syncthreads();

    const int b = blockIdx.y;
    const int pix = blockIdx.x*256 + tid;   // grid.x = 100 -> 25600 pixels

    float acc[64];
    #pragma unroll
    for (int m = 0; m < 64; m++) acc[m] = 0.f;

    #pragma unroll 1
    for (int ci = 0; ci < 64; ci++) {
        float xv = x[((size_t)(b*64 + ci))*HWSZ + pix];
        #pragma unroll
        for (int m = 0; m < 64; m++) acc[m] += s_w[m*64 + ci] * xv;
    }
    float g = g_gmap[(size_t)b*HWSZ + pix];
    float s = g_smap[(size_t)b*HWSZ + pix];
    #pragma unroll
    for (int m = 0; m < 64; m++)
        g_fusion[((size_t)(b*64 + m))*HWSZ + pix] = s * (g*acc[m] + s_be[m]);
}

// ---------------- K5: out = fc(t) + fc_b + residual ------------------------
__global__ __launch_bounds__(256)
void fc_k(const float* __restrict__ fcw, const float* __restrict__ fcb,
          const float* __restrict__ x, float* __restrict__ out)
{
    __shared__ float s_w[4096];
    __shared__ float s_b[64];
    const int tid = threadIdx.x;
    for (int i = tid; i < 4096; i += 256) s_w[i] = fcw[i];
    if (tid < 64) s_b[tid] = fcb[tid];
    __syncthreads();

    const int b = blockIdx.y;
    const int pix = blockIdx.x*256 + tid;

    float acc[64];
    #pragma unroll
    for (int m = 0; m < 64; m++) acc[m] = 0.f;

    #pragma unroll 1
    for (int ci = 0; ci < 64; ci++) {
        float tv = g_t[((size_t)(b*64 + ci))*HWSZ + pix];
        #pragma unroll
        for (int m = 0; m < 64; m++) acc[m] += s_w[m*64 + ci] * tv;
    }
    #pragma unroll
    for (int m = 0; m < 64; m++) {
        size_t idx = ((size_t)(b*64 + m))*HWSZ + pix;
        out[idx] = acc[m] + s_b[m] + x[idx];
    }
}

// ---------------------------------------------------------------------------
extern "C" void kernel_launch(void* const* d_in, const int* in_sizes, int n_in,
                              void* d_out, int out_size)
{
    (void)in_sizes; (void)n_in; (void)out_size;
    const float* x     = (const float*)d_in[0];
    const float* ba_w1 = (const float*)d_in[1];
    const float* ba_b1 = (const float*)d_in[2];
    const float* ba_w2 = (const float*)d_in[3];
    const float* ba_b2 = (const float*)d_in[4];
    // d_in[5..12]: offset branch — dead code in the reference, skipped.
    const float* rk5w  = (const float*)d_in[13];
    const float* rk5b  = (const float*)d_in[14];
    const float* rk7w  = (const float*)d_in[15];
    const float* rk7b  = (const float*)d_in[16];
    const float* lk5w  = (const float*)d_in[17];
    const float* lk5b  = (const float*)d_in[18];
    const float* lk7w  = (const float*)d_in[19];
    const float* lk7b  = (const float*)d_in[20];
    const float* sfw   = (const float*)d_in[21];
    const float* sfb   = (const float*)d_in[22];
    const float* sfg   = (const float*)d_in[23];
    const float* sfbb  = (const float*)d_in[24];
    const float* sfm   = (const float*)d_in[25];
    const float* sfv   = (const float*)d_in[26];
    const float* fcw   = (const float*)d_in[27];
    const float* fcb   = (const float*)d_in[28];
    float* out = (float*)d_out;

    float *pA32, *pFus, *pT;
    cudaGetSymbolAddress((void**)&pA32, g_A32);
    cudaGetSymbolAddress((void**)&pFus, g_fusion);
    cudaGetSymbolAddress((void**)&pT,   g_t);

    build_weff<<<16, 256>>>(rk5w, rk5b, rk7w, rk7b, lk5w, lk5b, lk7w, lk7b);

    dim3 grid(WW/16, HH/16, BB);
    conv3x3_k<64,32,0><<<grid, 256>>>(x, ba_w1, ba_b1,
                                      nullptr, nullptr, nullptr, nullptr, pA32);
    edge_attn_k<<<grid, 256>>>(x, ba_w2, ba_b2);
    fusion_k<<<dim3(HWSZ/256, BB), 256>>>(x);
    conv3x3_k<64,64,1><<<grid, 256>>>(pFus, sfw, sfb, sfg, sfbb, sfm, sfv, pT);
    fc_k<<<dim3(HWSZ/256, BB), 256>>>(fcw, fcb, x, out);
}